// round 16
// baseline (speedup 1.0000x reference)
#include <cuda_runtime.h>
#include <cuda_bf16.h>

// Problem constants (fixed by the dataset)
#define B    256
#define G    20000
#define NTF  1024
#define NPT  8     // nodes per TF
#define GPT  64    // genes per TF
#define EPS  1e-5f
#define SLOPE 0.01f

typedef unsigned long long u64;

// Packed fp32x2 FMA (Blackwell): d = a*b + d elementwise on 2 packed floats.
#define FMA2(d, a, b) asm("fma.rn.f32x2 %0, %1, %2, %0;" : "+l"(d) : "l"(a), "l"(b))
#define UNPACK2(lo, hi, v) asm("mov.b64 {%0, %1}, %2;" : "=f"(lo), "=f"(hi) : "l"(v))

// Scratch: x transposed to [G, B] for coalesced gene-row gathers. 20.48 MB.
__device__ float g_xT[(size_t)G * B];

// ---------------------------------------------------------------------------
// Kernel 1: transpose x [B, G] -> xT [G, B].  G = 625 * 32 exactly.
// ---------------------------------------------------------------------------
__global__ void __launch_bounds__(256) transpose_kernel(const float* __restrict__ x) {
    __shared__ float tile[32][33];
    const int g0 = blockIdx.x * 32;
    const int b0 = blockIdx.y * 32;
    const int tx = threadIdx.x;      // 0..31
    const int ty = threadIdx.y;      // 0..7

#pragma unroll
    for (int i = 0; i < 32; i += 8)
        tile[ty + i][tx] = x[(size_t)(b0 + ty + i) * G + (g0 + tx)];
    __syncthreads();
#pragma unroll
    for (int i = 0; i < 32; i += 8)
        g_xT[(size_t)(g0 + ty + i) * B + (b0 + tx)] = tile[tx][ty + i];
}

// ---------------------------------------------------------------------------
// Kernel 2: fused encoder. One 128-thread block per TF (grid = 1024).
//   R12 structure (MLP16 double-buffered gathers) with the FMA core swapped
//   to fma.rn.f32x2 against pre-duplicated {w,w} smem weights:
//   per gene: LDG.64 + 4 LDS.128 + 8 FFMA2 (vs 2 LDS.128 + 16 FFMA).
//   Gene indices loaded as int4 (1 LDS per 4 genes).
//   layer1 -> BN1 -> LeakyReLU -> layer2 -> BN2 -> LeakyReLU -> out.
// ---------------------------------------------------------------------------
__global__ void __launch_bounds__(128, 6) fused_encoder_kernel(
    const float* __restrict__ w1,
    const int*   __restrict__ in_idx1,
    const float* __restrict__ w2,
    float*       __restrict__ out)
{
    const int tid  = threadIdx.x;     // 0..127
    const int wrp  = tid >> 5;        // 0..3
    const int lane = tid & 31;
    const int t    = blockIdx.x;

    __shared__ __align__(16) float2 sw1d[NPT * GPT];  // [g*8 + j] = {w, w}, 4 KB
    __shared__ __align__(16) int    sg[GPT];          // gene offsets * B
    __shared__ float sw2[NPT];
    __shared__ float rsum[4][NPT + 2];                // per-warp partials
    __shared__ float rsq [4][NPT + 2];
    __shared__ float smean[NPT], srstd[NPT];
    __shared__ float zmean, zrstd;

    // ---- Stage duplicated weights + gene indices -----------------------------
#pragma unroll
    for (int i = tid; i < NPT * GPT; i += 128) {
        const int j = i >> 6;          // node
        const int g = i & 63;          // gene slot
        const float w = w1[t * (NPT * GPT) + i];
        sw1d[g * NPT + j] = make_float2(w, w);
    }
    if (tid < GPT) sg[tid]  = in_idx1[t * (NPT * GPT) + tid] * B;
    if (tid < NPT) sw2[tid] = w2[t * NPT + tid];
    __syncthreads();

    // ---- Layer 1: acc2[j] = packed pair over 2 batch elems -------------------
    u64 acc2[NPT];
#pragma unroll
    for (int j = 0; j < NPT; j++) acc2[j] = 0ull;

    const int boff = 2 * tid;

    // 8 genes of FFMA2 against a buffer of 8 packed x pairs
#define GENE8_FMA2(gb, xv)                                                     \
    {                                                                          \
        _Pragma("unroll")                                                      \
        for (int u = 0; u < 8; u++) {                                          \
            const ulonglong2 w01 = *(const ulonglong2*)&sw1d[((gb) + u) * NPT];      \
            const ulonglong2 w23 = *(const ulonglong2*)&sw1d[((gb) + u) * NPT + 2];  \
            FMA2(acc2[0], w01.x, xv[u]); FMA2(acc2[1], w01.y, xv[u]);          \
            FMA2(acc2[2], w23.x, xv[u]); FMA2(acc2[3], w23.y, xv[u]);          \
            const ulonglong2 w45 = *(const ulonglong2*)&sw1d[((gb) + u) * NPT + 4];  \
            const ulonglong2 w67 = *(const ulonglong2*)&sw1d[((gb) + u) * NPT + 6];  \
            FMA2(acc2[4], w45.x, xv[u]); FMA2(acc2[5], w45.y, xv[u]);          \
            FMA2(acc2[6], w67.x, xv[u]); FMA2(acc2[7], w67.y, xv[u]);          \
        }                                                                      \
    }

    // fetch 8 gene x-pairs (indices via 2 int4 loads)
#define FETCH8(dst, gb)                                                        \
    {                                                                          \
        const int4 i03 = *(const int4*)&sg[(gb)];                              \
        const int4 i47 = *(const int4*)&sg[(gb) + 4];                          \
        dst[0] = *(const u64*)&g_xT[i03.x + boff];                             \
        dst[1] = *(const u64*)&g_xT[i03.y + boff];                             \
        dst[2] = *(const u64*)&g_xT[i03.z + boff];                             \
        dst[3] = *(const u64*)&g_xT[i03.w + boff];                             \
        dst[4] = *(const u64*)&g_xT[i47.x + boff];                             \
        dst[5] = *(const u64*)&g_xT[i47.y + boff];                             \
        dst[6] = *(const u64*)&g_xT[i47.z + boff];                             \
        dst[7] = *(const u64*)&g_xT[i47.w + boff];                             \
    }

    u64 xa[8], xb[8];
    // prime: genes 0..15 in flight together (MLP ~16)
    FETCH8(xa, 0);
    FETCH8(xb, 8);

#pragma unroll
    for (int g0 = 0; g0 < GPT; g0 += 16) {
        GENE8_FMA2(g0, xa);
        if (g0 + 16 < GPT) FETCH8(xa, g0 + 16);
        GENE8_FMA2(g0 + 8, xb);
        if (g0 + 24 < GPT) FETCH8(xb, g0 + 24);
    }

    // unpack accumulators
    float2 acc[NPT];
#pragma unroll
    for (int j = 0; j < NPT; j++) UNPACK2(acc[j].x, acc[j].y, acc2[j]);

    // ---- BN1 stats: sum over 256 batch elems (128 threads x 2) per node ------
#pragma unroll
    for (int j = 0; j < NPT; j++) {
        float s  = acc[j].x + acc[j].y;
        float s2 = acc[j].x * acc[j].x + acc[j].y * acc[j].y;
#pragma unroll
        for (int o = 16; o > 0; o >>= 1) {
            s  += __shfl_xor_sync(0xffffffffu, s,  o);
            s2 += __shfl_xor_sync(0xffffffffu, s2, o);
        }
        if (lane == 0) { rsum[wrp][j] = s; rsq[wrp][j] = s2; }
    }
    __syncthreads();
    if (tid < NPT) {
        float s = 0.f, s2 = 0.f;
#pragma unroll
        for (int w = 0; w < 4; w++) { s += rsum[w][tid]; s2 += rsq[w][tid]; }
        const float m   = s * (1.f / B);
        const float var = s2 * (1.f / B) - m * m;
        smean[tid] = m;
        srstd[tid] = rsqrtf(var + EPS);
    }
    __syncthreads();

    // ---- BN1 + LeakyReLU + Layer 2 dot ---------------------------------------
    float z0 = 0.f, z1 = 0.f;
#pragma unroll
    for (int j = 0; j < NPT; j++) {
        const float m = smean[j], r = srstd[j], w = sw2[j];
        float v0 = (acc[j].x - m) * r;  v0 = (v0 > 0.f) ? v0 : SLOPE * v0;
        float v1 = (acc[j].y - m) * r;  v1 = (v1 > 0.f) ? v1 : SLOPE * v1;
        z0 = fmaf(w, v0, z0);
        z1 = fmaf(w, v1, z1);
    }

    // ---- BN2 stats over 256 batch values -------------------------------------
    {
        float s = z0 + z1, s2 = z0 * z0 + z1 * z1;
#pragma unroll
        for (int o = 16; o > 0; o >>= 1) {
            s  += __shfl_xor_sync(0xffffffffu, s,  o);
            s2 += __shfl_xor_sync(0xffffffffu, s2, o);
        }
        if (lane == 0) { rsum[wrp][NPT] = s; rsq[wrp][NPT] = s2; }
    }
    __syncthreads();
    if (tid == 0) {
        float s = 0.f, s2 = 0.f;
#pragma unroll
        for (int w = 0; w < 4; w++) { s += rsum[w][NPT]; s2 += rsq[w][NPT]; }
        const float m   = s * (1.f / B);
        const float var = s2 * (1.f / B) - m * m;
        zmean = m;
        zrstd = rsqrtf(var + EPS);
    }
    __syncthreads();

    const float m = zmean, r = zrstd;
    float v0 = (z0 - m) * r;  v0 = (v0 > 0.f) ? v0 : SLOPE * v0;
    float v1 = (z1 - m) * r;  v1 = (v1 > 0.f) ? v1 : SLOPE * v1;
    out[(size_t)(boff)     * NTF + t] = v0;
    out[(size_t)(boff + 1) * NTF + t] = v1;
}

// ---------------------------------------------------------------------------
extern "C" void kernel_launch(void* const* d_in, const int* in_sizes, int n_in,
                              void* d_out, int out_size) {
    const float* x       = (const float*)d_in[0];
    const float* w1      = (const float*)d_in[1];
    const int*   in_idx1 = (const int*)  d_in[2];
    const float* w2      = (const float*)d_in[4];
    float*       out     = (float*)d_out;

    dim3 tb(32, 8);
    dim3 tg(G / 32, B / 32);           // 625 x 8, exact
    transpose_kernel<<<tg, tb>>>(x);
    fused_encoder_kernel<<<NTF, 128>>>(w1, in_idx1, w2, out);
}

// round 17
// speedup vs baseline: 1.6245x; 1.6245x over previous
#include <cuda_runtime.h>
#include <cuda_bf16.h>
#include <cstdint>

// Problem constants (fixed by the dataset)
#define B    256
#define G    20000
#define NTF  1024
#define NPT  8     // nodes per TF
#define GPT  64    // genes per TF
#define EPS  1e-5f
#define SLOPE 0.01f

#define CG    8                    // genes per chunk
#define NCH   (GPT / CG)           // 8 chunks
#define CHB   (CG * B * 4)         // 8192 bytes per chunk

// Scratch: x transposed to [G, B] for coalesced gene-row reads. 20.48 MB.
__device__ float g_xT[(size_t)G * B];

// ---------------------------------------------------------------------------
// Kernel 1: transpose x [B, G] -> xT [G, B].  G = 625 * 32 exactly.
// ---------------------------------------------------------------------------
__global__ void __launch_bounds__(256) transpose_kernel(const float* __restrict__ x) {
    __shared__ float tile[32][33];
    const int g0 = blockIdx.x * 32;
    const int b0 = blockIdx.y * 32;
    const int tx = threadIdx.x;      // 0..31
    const int ty = threadIdx.y;      // 0..7

#pragma unroll
    for (int i = 0; i < 32; i += 8)
        tile[ty + i][tx] = x[(size_t)(b0 + ty + i) * G + (g0 + tx)];
    __syncthreads();
#pragma unroll
    for (int i = 0; i < 32; i += 8)
        g_xT[(size_t)(g0 + ty + i) * B + (b0 + tx)] = tile[tx][ty + i];
}

// ---------------------------------------------------------------------------
// cp.async helpers
// ---------------------------------------------------------------------------
__device__ __forceinline__ uint32_t smem_u32(const void* p) {
    uint32_t a;
    asm("{ .reg .u64 t; cvta.to.shared.u64 t, %1; cvt.u32.u64 %0, t; }" : "=r"(a) : "l"(p));
    return a;
}
#define CPASYNC16(dst, src) \
    asm volatile("cp.async.cg.shared.global [%0], [%1], 16;" :: "r"(dst), "l"(src) : "memory")
#define CPCOMMIT() asm volatile("cp.async.commit_group;" ::: "memory")
#define CPWAIT(N)  asm volatile("cp.async.wait_group " #N ";" ::: "memory")

// ---------------------------------------------------------------------------
// Kernel 2: fused encoder. One 128-thread block per TF (grid = 1024).
//   Gene rows staged to smem with per-thread cp.async.cg (16B each, zero
//   register/scoreboard cost): 4-buffer ring, 8 genes/chunk, 3 chunks
//   (24 genes) in flight. Consumer path is pure smem.
//   Each thread owns 2 batch elements (float2).
//   layer1 -> BN1 -> LeakyReLU -> layer2 -> BN2 -> LeakyReLU -> out.
// ---------------------------------------------------------------------------
__global__ void __launch_bounds__(128, 6) fused_encoder_kernel(
    const float* __restrict__ w1,
    const int*   __restrict__ in_idx1,
    const float* __restrict__ w2,
    float*       __restrict__ out)
{
    const int tid  = threadIdx.x;     // 0..127
    const int wrp  = tid >> 5;        // 0..3
    const int lane = tid & 31;
    const int t    = blockIdx.x;

    __shared__ __align__(16) float xbuf[4][CG][B];   // 32 KB ring
    __shared__ __align__(16) float sw1t[NPT * GPT];  // [g*8 + j], 2 KB
    __shared__ __align__(16) int   sg[GPT];          // gene offsets * B
    __shared__ float sw2[NPT];
    __shared__ float rsum[4][NPT + 2];
    __shared__ float rsq [4][NPT + 2];
    __shared__ float smean[NPT], srstd[NPT];
    __shared__ float zmean, zrstd;

    const uint32_t xb_base = smem_u32(&xbuf[0][0][0]);
    const int      tb16    = tid * 16;

    // ---- Prologue: fire cp.async for chunks 0..2 using global idx loads ------
#pragma unroll
    for (int ch = 0; ch < 3; ch++) {
        const uint32_t dbase = xb_base + ch * CHB;
#pragma unroll
        for (int i = 0; i < 4; i++) {
            const int o    = i * 2048 + tb16;            // byte offset in chunk
            const int gene = ch * CG + (o >> 10);
            const int goff = __ldg(&in_idx1[t * (NPT * GPT) + gene]) * B;
            const char* src = (const char*)g_xT + ((size_t)(unsigned)goff << 2) + (o & 1023);
            CPASYNC16(dbase + o, src);
        }
        CPCOMMIT();
    }

    // ---- Stage weights (transposed) + gene indices (overlaps cp.async) -------
#pragma unroll
    for (int i = tid; i < NPT * GPT; i += 128) {
        const int j = i >> 6;          // node
        const int g = i & 63;          // gene slot
        sw1t[g * NPT + j] = w1[t * (NPT * GPT) + i];
    }
    if (tid < GPT) sg[tid]  = in_idx1[t * (NPT * GPT) + tid] * B;
    if (tid < NPT) sw2[tid] = w2[t * NPT + tid];
    __syncthreads();   // sg/sw1t visible; also first ring barrier baseline

    // ---- Layer 1 mainloop -----------------------------------------------------
    float2 acc[NPT];
#pragma unroll
    for (int j = 0; j < NPT; j++) acc[j] = make_float2(0.f, 0.f);

    const int boff = 2 * tid;

#define FILL(cidx)                                                             \
    {                                                                          \
        const uint32_t dbase = xb_base + ((cidx) & 3) * CHB;                   \
        _Pragma("unroll")                                                      \
        for (int i = 0; i < 4; i++) {                                          \
            const int o    = i * 2048 + tb16;                                  \
            const int gene = (cidx) * CG + (o >> 10);                          \
            const char* src = (const char*)g_xT                                \
                + ((size_t)(unsigned)sg[gene] << 2) + (o & 1023);              \
            CPASYNC16(dbase + o, src);                                         \
        }                                                                      \
        CPCOMMIT();                                                            \
    }

#define CONSUME(cidx)                                                          \
    {                                                                          \
        const int bq = (cidx) & 3;                                             \
        float2 xv[CG];                                                         \
        _Pragma("unroll")                                                      \
        for (int u = 0; u < CG; u++)                                           \
            xv[u] = *(const float2*)&xbuf[bq][u][boff];                        \
        _Pragma("unroll")                                                      \
        for (int u = 0; u < CG; u++) {                                         \
            const int gg = (cidx) * CG + u;                                    \
            const float4 wa = *(const float4*)&sw1t[gg * NPT];                 \
            const float4 wb = *(const float4*)&sw1t[gg * NPT + 4];             \
            acc[0].x = fmaf(wa.x, xv[u].x, acc[0].x);                          \
            acc[0].y = fmaf(wa.x, xv[u].y, acc[0].y);                          \
            acc[1].x = fmaf(wa.y, xv[u].x, acc[1].x);                          \
            acc[1].y = fmaf(wa.y, xv[u].y, acc[1].y);                          \
            acc[2].x = fmaf(wa.z, xv[u].x, acc[2].x);                          \
            acc[2].y = fmaf(wa.z, xv[u].y, acc[2].y);                          \
            acc[3].x = fmaf(wa.w, xv[u].x, acc[3].x);                          \
            acc[3].y = fmaf(wa.w, xv[u].y, acc[3].y);                          \
            acc[4].x = fmaf(wb.x, xv[u].x, acc[4].x);                          \
            acc[4].y = fmaf(wb.x, xv[u].y, acc[4].y);                          \
            acc[5].x = fmaf(wb.y, xv[u].x, acc[5].x);                          \
            acc[5].y = fmaf(wb.y, xv[u].y, acc[5].y);                          \
            acc[6].x = fmaf(wb.z, xv[u].x, acc[6].x);                          \
            acc[6].y = fmaf(wb.z, xv[u].y, acc[6].y);                          \
            acc[7].x = fmaf(wb.w, xv[u].x, acc[7].x);                          \
            acc[7].y = fmaf(wb.w, xv[u].y, acc[7].y);                          \
        }                                                                      \
    }

    // iter c: wait chunk c ready -> barrier -> consume c -> fill c+3.
    // Fill target buf (c+3)&3 == (c-1)&3 was consumed in iter c-1, and this
    // iter's barrier orders that consume before the refill: safe.
    // Groups committed: 3 prologue + fills at c=0..4 (chunks 3..7) = 8 total.
#define ITER(c, WAITMACRO)                                                     \
    {                                                                          \
        WAITMACRO;                                                             \
        __syncthreads();                                                       \
        CONSUME(c);                                                            \
        if ((c) + 3 < NCH) FILL((c) + 3);                                      \
    }

    ITER(0, CPWAIT(2))
    ITER(1, CPWAIT(2))
    ITER(2, CPWAIT(2))
    ITER(3, CPWAIT(2))
    ITER(4, CPWAIT(2))
    ITER(5, CPWAIT(2))
    ITER(6, CPWAIT(1))
    ITER(7, CPWAIT(0))

    // ---- BN1 stats: sum over 256 batch elems (128 threads x 2) per node ------
#pragma unroll
    for (int j = 0; j < NPT; j++) {
        float s  = acc[j].x + acc[j].y;
        float s2 = acc[j].x * acc[j].x + acc[j].y * acc[j].y;
#pragma unroll
        for (int o = 16; o > 0; o >>= 1) {
            s  += __shfl_xor_sync(0xffffffffu, s,  o);
            s2 += __shfl_xor_sync(0xffffffffu, s2, o);
        }
        if (lane == 0) { rsum[wrp][j] = s; rsq[wrp][j] = s2; }
    }
    __syncthreads();
    if (tid < NPT) {
        float s = 0.f, s2 = 0.f;
#pragma unroll
        for (int w = 0; w < 4; w++) { s += rsum[w][tid]; s2 += rsq[w][tid]; }
        const float m   = s * (1.f / B);
        const float var = s2 * (1.f / B) - m * m;
        smean[tid] = m;
        srstd[tid] = rsqrtf(var + EPS);
    }
    __syncthreads();

    // ---- BN1 + LeakyReLU + Layer 2 dot ---------------------------------------
    float z0 = 0.f, z1 = 0.f;
#pragma unroll
    for (int j = 0; j < NPT; j++) {
        const float m = smean[j], r = srstd[j], w = sw2[j];
        float v0 = (acc[j].x - m) * r;  v0 = (v0 > 0.f) ? v0 : SLOPE * v0;
        float v1 = (acc[j].y - m) * r;  v1 = (v1 > 0.f) ? v1 : SLOPE * v1;
        z0 = fmaf(w, v0, z0);
        z1 = fmaf(w, v1, z1);
    }

    // ---- BN2 stats over 256 batch values -------------------------------------
    {
        float s = z0 + z1, s2 = z0 * z0 + z1 * z1;
#pragma unroll
        for (int o = 16; o > 0; o >>= 1) {
            s  += __shfl_xor_sync(0xffffffffu, s,  o);
            s2 += __shfl_xor_sync(0xffffffffu, s2, o);
        }
        if (lane == 0) { rsum[wrp][NPT] = s; rsq[wrp][NPT] = s2; }
    }
    __syncthreads();
    if (tid == 0) {
        float s = 0.f, s2 = 0.f;
#pragma unroll
        for (int w = 0; w < 4; w++) { s += rsum[w][NPT]; s2 += rsq[w][NPT]; }
        const float m   = s * (1.f / B);
        const float var = s2 * (1.f / B) - m * m;
        zmean = m;
        zrstd = rsqrtf(var + EPS);
    }
    __syncthreads();

    const float m = zmean, r = zrstd;
    float v0 = (z0 - m) * r;  v0 = (v0 > 0.f) ? v0 : SLOPE * v0;
    float v1 = (z1 - m) * r;  v1 = (v1 > 0.f) ? v1 : SLOPE * v1;
    out[(size_t)(boff)     * NTF + t] = v0;
    out[(size_t)(boff + 1) * NTF + t] = v1;
}

// ---------------------------------------------------------------------------
extern "C" void kernel_launch(void* const* d_in, const int* in_sizes, int n_in,
                              void* d_out, int out_size) {
    const float* x       = (const float*)d_in[0];
    const float* w1      = (const float*)d_in[1];
    const int*   in_idx1 = (const int*)  d_in[2];
    const float* w2      = (const float*)d_in[4];
    float*       out     = (float*)d_out;

    dim3 tb(32, 8);
    dim3 tg(G / 32, B / 32);           // 625 x 8, exact
    transpose_kernel<<<tg, tb>>>(x);
    fused_encoder_kernel<<<NTF, 128>>>(w1, in_idx1, w2, out);
}